// round 16
// baseline (speedup 1.0000x reference)
#include <cuda_runtime.h>
#include <cuda_fp16.h>
#include <cstdint>

#define D_MODEL 1024
#define N_TOK   2048
#define N_HEADS 16
#define HEAD_D  64
#define SEQ     512
#define NB      4
#define FFN_D   4096
#define NEXP    8
#define CAPV    512

typedef __half hf;

// ================= device scratch =================
__device__ hf g_wq1[1048576], g_wk1[1048576], g_wv1[1048576], g_wo1[1048576];
__device__ hf g_w11[33554432], g_w21[33554432];
__device__ hf g_h1h[2097152];
__device__ hf g_h2h[2097152];
__device__ float g_h2[2097152];
__device__ hf g_qh[2097152];
__device__ hf g_kh[2097152];
__device__ hf g_vh[2097152];
__device__ hf g_ath[2097152];
__device__ hf g_midh[16777216];
__device__ float g_y[4194304];
__device__ int   g_top1[N_TOK], g_top2[N_TOK];
__device__ float g_p1[N_TOK], g_p2[N_TOK];
__device__ int   g_s1[N_TOK], g_s2[N_TOK];
__device__ float g_g1[N_TOK], g_g2[N_TOK];
__device__ int   g_disp[NEXP * CAPV];

// ================= helpers =================
__device__ __forceinline__ uint32_t smem_u32(const void* p) {
    uint32_t a;
    asm("{ .reg .u64 t; cvta.to.shared.u64 t, %1; cvt.u32.u64 %0, t; }" : "=r"(a) : "l"(p));
    return a;
}
__device__ __forceinline__ void ldsm_x4(uint32_t* r, uint32_t addr) {
    asm volatile("ldmatrix.sync.aligned.m8n8.x4.shared.b16 {%0,%1,%2,%3}, [%4];"
        : "=r"(r[0]), "=r"(r[1]), "=r"(r[2]), "=r"(r[3]) : "r"(addr));
}
__device__ __forceinline__ void ldsm_x4t(uint32_t* r, uint32_t addr) {
    asm volatile("ldmatrix.sync.aligned.m8n8.x4.trans.shared.b16 {%0,%1,%2,%3}, [%4];"
        : "=r"(r[0]), "=r"(r[1]), "=r"(r[2]), "=r"(r[3]) : "r"(addr));
}
__device__ __forceinline__ void mma16816(float* c, const uint32_t* a, uint32_t b0, uint32_t b1) {
    asm volatile(
        "mma.sync.aligned.m16n8k16.row.col.f32.f16.f16.f32 "
        "{%0,%1,%2,%3}, {%4,%5,%6,%7}, {%8,%9}, {%0,%1,%2,%3};"
        : "+f"(c[0]), "+f"(c[1]), "+f"(c[2]), "+f"(c[3])
        : "r"(a[0]), "r"(a[1]), "r"(a[2]), "r"(a[3]), "r"(b0), "r"(b1));
}
__device__ __forceinline__ void cp16(uint32_t dst, const void* src) {
    asm volatile("cp.async.cg.shared.global [%0], [%1], 16;" :: "r"(dst), "l"(src) : "memory");
}
#define CP_COMMIT() asm volatile("cp.async.commit_group;" ::: "memory")
__device__ __forceinline__ uint32_t pack2s(float x, float y) {
    return (uint32_t)__half_as_ushort(__float2half_rn(x)) |
           ((uint32_t)__half_as_ushort(__float2half_rn(y)) << 16);
}

// ================= weight rounding: 16 floats/thread, MLP=4 loads, 16B stores =================
__global__ __launch_bounds__(256)
void round_pass(const float* __restrict__ src, hf* __restrict__ dst, long n16) {
    for (long i = blockIdx.x * 256 + threadIdx.x; i < n16; i += (long)gridDim.x * 256) {
        const float4* s = (const float4*)(src + i * 16);
        float4 a = s[0], b = s[1], c = s[2], d = s[3];
        uint4 o0, o1;
        o0.x = pack2s(a.x, a.y); o0.y = pack2s(a.z, a.w);
        o0.z = pack2s(b.x, b.y); o0.w = pack2s(b.z, b.w);
        o1.x = pack2s(c.x, c.y); o1.y = pack2s(c.z, c.w);
        o1.z = pack2s(d.x, d.y); o1.w = pack2s(d.z, d.w);
        uint4* dv = (uint4*)(dst + i * 16);
        dv[0] = o0; dv[1] = o1;
    }
}

__global__ __launch_bounds__(256)
void round_attn(const float* __restrict__ wq, const float* __restrict__ wk,
                const float* __restrict__ wv, const float* __restrict__ wo,
                hf* __restrict__ q1, hf* __restrict__ k1,
                hf* __restrict__ v1, hf* __restrict__ o1) {
    int z = blockIdx.z;
    const float* src = (z == 0) ? wq : (z == 1) ? wk : (z == 2) ? wv : wo;
    hf* dst = (z == 0) ? q1 : (z == 1) ? k1 : (z == 2) ? v1 : o1;
    const long n16 = 65536;
    for (long i = blockIdx.x * 256 + threadIdx.x; i < n16; i += (long)gridDim.x * 256) {
        const float4* s = (const float4*)(src + i * 16);
        float4 a = s[0], b = s[1], c = s[2], d = s[3];
        uint4 o0, o1v;
        o0.x = pack2s(a.x, a.y); o0.y = pack2s(a.z, a.w);
        o0.z = pack2s(b.x, b.y); o0.w = pack2s(b.z, b.w);
        o1v.x = pack2s(c.x, c.y); o1v.y = pack2s(c.z, c.w);
        o1v.z = pack2s(d.x, d.y); o1v.w = pack2s(d.z, d.w);
        uint4* dv = (uint4*)(dst + i * 16);
        dv[0] = o0; dv[1] = o1v;
    }
}

// ================= fp16 HMMA GEMM: CTA TMx128, Kc=32, 3-stage cp.async, 2 CTAs/SM =================
template <int TMv, bool RELU, bool GATHER, bool MULTI, bool OSPLIT>
__global__ __launch_bounds__(256, 2)
void gemm_mma(const hf* __restrict__ A,
              const hf* __restrict__ B0, const hf* __restrict__ B1,
              const hf* __restrict__ B2,
              const float* __restrict__ bi0, const float* __restrict__ bi1,
              const float* __restrict__ bi2,
              float* __restrict__ oF0,
              hf* __restrict__ oH0, hf* __restrict__ oH1, hf* __restrict__ oH2,
              float s0, float s1, float s2,
              const float* __restrict__ resid, const int* __restrict__ gather,
              int K, int N,
              long aStride, long bStride, long biStride, long oStride) {
    constexpr int A_SZ = TMv * 80;
    constexpr int B_O  = A_SZ;
    constexpr int STGB = A_SZ + 8192;
    constexpr int MT   = TMv / 32;
    constexpr int WMROWS = TMv / 2;

    extern __shared__ char sm[];
    uint32_t sb = smem_u32(sm);
    int tid = threadIdx.x, wid = tid >> 5, lane = tid & 31;
    int z = blockIdx.z;
    int m0 = blockIdx.y * TMv, n0 = blockIdx.x * 128;

    const hf* B; const float* bi; float scale;
    float* oF = nullptr; hf* oH = nullptr;
    if (MULTI) {
        B = (z == 0) ? B0 : (z == 1) ? B1 : B2;
        bi = (z == 0) ? bi0 : (z == 1) ? bi1 : bi2;
        scale = (z == 0) ? s0 : (z == 1) ? s1 : s2;
        oH = (z == 0) ? oH0 : (z == 1) ? oH1 : oH2;
    } else {
        B = B0 + (long)z * bStride;
        bi = bi0 + (long)z * biStride;
        scale = s0;
        if (OSPLIT) oH = oH0 + (long)z * oStride;
        else oF = oF0 + (long)z * oStride;
    }
    const hf* Az = A + (MULTI ? 0 : (long)z * aStride);
    const int* gz = GATHER ? (gather + z * CAPV) : nullptr;

    int aR0 = tid >> 2, aC0 = (tid & 3) * 8;
    long aRow0 = GATHER ? (long)gz[m0 + aR0] : (long)(m0 + aR0);
    long aG0 = aRow0 * K + aC0;
    int aD0 = aR0 * 80 + aC0 * 2;
    long aG1 = 0; int aD1 = 0;
    if (TMv == 128) {
        int aR1 = (tid + 256) >> 2, aC1 = ((tid + 256) & 3) * 8;
        long aRow1 = GATHER ? (long)gz[m0 + aR1] : (long)(m0 + aR1);
        aG1 = aRow1 * K + aC1;
        aD1 = aR1 * 80 + aC1 * 2;
    }

    int bK0 = tid >> 4, bN0 = (tid & 15) * 8;
    long bG0 = (long)bK0 * N + n0 + bN0;
    int bD0 = bK0 * 256 + ((bN0 * 2) ^ ((bK0 & 7) << 4));

    int nCh = K >> 5;
#pragma unroll
    for (int pre = 0; pre < 2; pre++) {
        uint32_t base = sb + (uint32_t)pre * STGB;
        int k0 = pre << 5;
        long ko = (long)k0 * N;
        cp16(base + aD0, Az + aG0 + k0);
        if (TMv == 128) cp16(base + aD1, Az + aG1 + k0);
        cp16(base + B_O + bD0, B + ko + bG0);
        cp16(base + B_O + bD0 + 4096, B + ko + bG0 + 16L * N);
        CP_COMMIT();
    }

    float c[MT][4][4];
#pragma unroll
    for (int mt = 0; mt < MT; mt++)
#pragma unroll
        for (int nt = 0; nt < 4; nt++)
#pragma unroll
            for (int f = 0; f < 4; f++) c[mt][nt][f] = 0.f;

    int wm = wid >> 2, wn = wid & 3;
    int aRowOff = (lane & 7) + ((lane >> 3) & 1) * 8;
    int aColSel = ((lane >> 4) & 1) * 16;
    int bKoff = (lane & 7) + ((lane >> 3) & 1) * 8;
    int bN8 = ((lane >> 4) & 1) * 8;

    for (int ch = 0; ch < nCh; ch++) {
        if (ch + 1 < nCh) asm volatile("cp.async.wait_group 1;" ::: "memory");
        else              asm volatile("cp.async.wait_group 0;" ::: "memory");
        __syncthreads();
        if (ch + 2 < nCh) {
            int chn = ch + 2;
            uint32_t base = sb + (uint32_t)(chn % 3) * STGB;
            int k0 = chn << 5;
            long ko = (long)k0 * N;
            cp16(base + aD0, Az + aG0 + k0);
            if (TMv == 128) cp16(base + aD1, Az + aG1 + k0);
            cp16(base + B_O + bD0, B + ko + bG0);
            cp16(base + B_O + bD0 + 4096, B + ko + bG0 + 16L * N);
            CP_COMMIT();
        }
        uint32_t sbuf = sb + (uint32_t)(ch % 3) * STGB;
#pragma unroll
        for (int ks = 0; ks < 2; ks++) {
            uint32_t ah[MT][4];
#pragma unroll
            for (int mt = 0; mt < MT; mt++) {
                uint32_t ro = (wm * WMROWS + mt * 16 + aRowOff) * 80 + ks * 32 + aColSel;
                ldsm_x4(ah[mt], sbuf + ro);
            }
#pragma unroll
            for (int nb = 0; nb < 2; nb++) {
                uint32_t bhf[4];
                int kk = ks * 16 + bKoff;
                int nn = wn * 32 + nb * 16 + bN8;
                uint32_t off = kk * 256 + ((nn * 2) ^ ((kk & 7) << 4));
                ldsm_x4t(bhf, sbuf + B_O + off);
#pragma unroll
                for (int hfk = 0; hfk < 2; hfk++) {
                    int nt = nb * 2 + hfk;
#pragma unroll
                    for (int mt = 0; mt < MT; mt++)
                        mma16816(c[mt][nt], ah[mt], bhf[hfk * 2], bhf[hfk * 2 + 1]);
                }
            }
        }
    }

    int r0 = m0 + wm * WMROWS + (lane >> 2);
    int col0 = n0 + wn * 32 + (lane & 3) * 2;
#pragma unroll
    for (int mt = 0; mt < MT; mt++) {
#pragma unroll
        for (int nt = 0; nt < 4; nt++) {
            int row = r0 + mt * 16;
            int cn = col0 + nt * 8;
            float2 bb = *(const float2*)(bi + cn);
            float v0x = (c[mt][nt][0] + bb.x) * scale;
            float v0y = (c[mt][nt][1] + bb.y) * scale;
            float v1x = (c[mt][nt][2] + bb.x) * scale;
            float v1y = (c[mt][nt][3] + bb.y) * scale;
            if (resid) {
                float2 ra = *(const float2*)(resid + (long)row * N + cn);
                float2 rb = *(const float2*)(resid + (long)(row + 8) * N + cn);
                v0x += ra.x; v0y += ra.y; v1x += rb.x; v1y += rb.y;
            }
            if (RELU) {
                v0x = fmaxf(v0x, 0.f); v0y = fmaxf(v0y, 0.f);
                v1x = fmaxf(v1x, 0.f); v1y = fmaxf(v1y, 0.f);
            }
            if (OSPLIT) {
                *(uint32_t*)(oH + (long)row * N + cn) = pack2s(v0x, v0y);
                *(uint32_t*)(oH + (long)(row + 8) * N + cn) = pack2s(v1x, v1y);
            } else {
                *(float2*)(oF + (long)row * N + cn) = make_float2(v0x, v0y);
                *(float2*)(oF + (long)(row + 8) * N + cn) = make_float2(v1x, v1y);
            }
        }
    }
}

// ================= fused flash attention =================
#define FA_Q  0
#define FA_K  18432
#define FA_V  27648
#define FA_P  35840
#define FA_M  52224
#define FA_L  52736
#define FA_AL 53248
#define FA_PM 53760
#define FA_PS 55808
#define FA_SMEM 57856

__global__ __launch_bounds__(256, 2)
void flash_attn(const hf* __restrict__ qh, const hf* __restrict__ kh,
                const hf* __restrict__ vh, hf* __restrict__ oh) {
    extern __shared__ char sm[];
    uint32_t sb = smem_u32(sm);
    float* M  = (float*)(sm + FA_M);
    float* L  = (float*)(sm + FA_L);
    float* AL = (float*)(sm + FA_AL);
    float* PM = (float*)(sm + FA_PM);
    float* PS = (float*)(sm + FA_PS);

    int tid = threadIdx.x, wid = tid >> 5, lane = tid & 31;
    int bh = blockIdx.y;
    int b = bh >> 4, h = bh & 15;
    int m0 = blockIdx.x * 128;

#pragma unroll
    for (int i = 0; i < 4; i++) {
        int v = tid + 256 * i;
        int row = v >> 3, c8 = (v & 7) * 8;
        long qg = (long)(b * SEQ + m0 + row) * D_MODEL + h * HEAD_D + c8;
        *(uint4*)(sm + FA_Q + row * 144 + c8 * 2) = *(const uint4*)(qh + qg);
    }
    if (tid < 128) { M[tid] = -1e30f; L[tid] = 0.f; }

    int wm = wid >> 2, wn = wid & 3;
    int rowOff = (lane & 7) + ((lane >> 3) & 1) * 8;
    int colSel = ((lane >> 4) & 1) * 16;
    int bKoff = rowOff;
    int bN8 = colSel >> 1;

    float oc[4][2][4];
#pragma unroll
    for (int mt = 0; mt < 4; mt++)
#pragma unroll
        for (int nt = 0; nt < 2; nt++)
#pragma unroll
            for (int f = 0; f < 4; f++) oc[mt][nt][f] = 0.f;

    int qr = lane >> 2;
    int qc = (lane & 3) * 2;

    for (int j = 0; j < SEQ / 64; j++) {
        __syncthreads();
#pragma unroll
        for (int i = 0; i < 2; i++) {
            int v = tid + 256 * i;
            int row = v >> 3, c8 = (v & 7) * 8;
            long kg = (long)(b * SEQ + j * 64 + row) * D_MODEL + h * HEAD_D + c8;
            *(uint4*)(sm + FA_K + row * 144 + c8 * 2) = *(const uint4*)(kh + kg);
            *(uint4*)(sm + FA_V + row * 128 + ((c8 * 2) ^ ((row & 7) << 4))) =
                *(const uint4*)(vh + kg);
        }
        __syncthreads();

        float c[4][2][4];
#pragma unroll
        for (int mt = 0; mt < 4; mt++)
#pragma unroll
            for (int nt = 0; nt < 2; nt++)
#pragma unroll
                for (int f = 0; f < 4; f++) c[mt][nt][f] = 0.f;
#pragma unroll
        for (int ks = 0; ks < 4; ks++) {
            uint32_t ah[4][4];
#pragma unroll
            for (int mt = 0; mt < 4; mt++) {
                uint32_t ro = (wm * 64 + mt * 16 + rowOff) * 144 + ks * 32 + colSel;
                ldsm_x4(ah[mt], sb + FA_Q + ro);
            }
            uint32_t bh_[4];
            {
                uint32_t ro = (wn * 16 + rowOff) * 144 + ks * 32 + colSel;
                ldsm_x4(bh_, sb + FA_K + ro);
            }
#pragma unroll
            for (int mt = 0; mt < 4; mt++)
#pragma unroll
                for (int nt = 0; nt < 2; nt++)
                    mma16816(c[mt][nt], ah[mt], bh_[nt], bh_[nt + 2]);
        }

#pragma unroll
        for (int mt = 0; mt < 4; mt++) {
            float mA = fmaxf(fmaxf(c[mt][0][0], c[mt][0][1]), fmaxf(c[mt][1][0], c[mt][1][1]));
            float mB = fmaxf(fmaxf(c[mt][0][2], c[mt][0][3]), fmaxf(c[mt][1][2], c[mt][1][3]));
#pragma unroll
            for (int o = 1; o <= 2; o <<= 1) {
                mA = fmaxf(mA, __shfl_xor_sync(~0u, mA, o));
                mB = fmaxf(mB, __shfl_xor_sync(~0u, mB, o));
            }
            if ((lane & 3) == 0) {
                int rA = wm * 64 + mt * 16 + qr;
                PM[rA * 4 + wn] = mA;
                PM[(rA + 8) * 4 + wn] = mB;
            }
        }
        __syncthreads();

#pragma unroll
        for (int mt = 0; mt < 4; mt++) {
            int rA = wm * 64 + mt * 16 + qr;
            int rB = rA + 8;
            float mnA = fmaxf(M[rA], fmaxf(fmaxf(PM[rA * 4], PM[rA * 4 + 1]),
                                           fmaxf(PM[rA * 4 + 2], PM[rA * 4 + 3])));
            float mnB = fmaxf(M[rB], fmaxf(fmaxf(PM[rB * 4], PM[rB * 4 + 1]),
                                           fmaxf(PM[rB * 4 + 2], PM[rB * 4 + 3])));
            float sA = 0.f, sB = 0.f;
#pragma unroll
            for (int nt = 0; nt < 2; nt++) {
                float p0 = expf(c[mt][nt][0] - mnA);
                float p1 = expf(c[mt][nt][1] - mnA);
                float p2 = expf(c[mt][nt][2] - mnB);
                float p3 = expf(c[mt][nt][3] - mnB);
                sA += p0 + p1; sB += p2 + p3;
                int cn = wn * 16 + nt * 8 + qc;
                *(uint32_t*)(sm + FA_P + rA * 128 + ((cn * 2) ^ ((rA & 7) << 4))) = pack2s(p0, p1);
                *(uint32_t*)(sm + FA_P + rB * 128 + ((cn * 2) ^ ((rB & 7) << 4))) = pack2s(p2, p3);
            }
#pragma unroll
            for (int o = 1; o <= 2; o <<= 1) {
                sA += __shfl_xor_sync(~0u, sA, o);
                sB += __shfl_xor_sync(~0u, sB, o);
            }
            if ((lane & 3) == 0) {
                PS[rA * 4 + wn] = sA;
                PS[rB * 4 + wn] = sB;
            }
        }
        __syncthreads();

        if (tid < 128) {
            int r = tid;
            float mo = M[r];
            float mn = fmaxf(mo, fmaxf(fmaxf(PM[r * 4], PM[r * 4 + 1]),
                                       fmaxf(PM[r * 4 + 2], PM[r * 4 + 3])));
            float a = expf(mo - mn);
            AL[r] = a;
            L[r] = a * L[r] + PS[r * 4] + PS[r * 4 + 1] + PS[r * 4 + 2] + PS[r * 4 + 3];
            M[r] = mn;
        }
        __syncthreads();

#pragma unroll
        for (int mt = 0; mt < 4; mt++) {
            int rA = wm * 64 + mt * 16 + qr;
            float aA = AL[rA], aB = AL[rA + 8];
#pragma unroll
            for (int nt = 0; nt < 2; nt++) {
                oc[mt][nt][0] *= aA; oc[mt][nt][1] *= aA;
                oc[mt][nt][2] *= aB; oc[mt][nt][3] *= aB;
            }
        }
#pragma unroll
        for (int ks = 0; ks < 4; ks++) {
            uint32_t pa[4][4];
#pragma unroll
            for (int mt = 0; mt < 4; mt++) {
                int row = wm * 64 + mt * 16 + rowOff;
                uint32_t ro = row * 128 + (((uint32_t)(ks * 32 + colSel)) ^ ((row & 7) << 4));
                ldsm_x4(pa[mt], sb + FA_P + ro);
            }
            uint32_t vb[4];
            {
                int kk = ks * 16 + bKoff;
                int nn = wn * 16 + bN8;
                uint32_t off = kk * 128 + ((nn * 2) ^ ((kk & 7) << 4));
                ldsm_x4t(vb, sb + FA_V + off);
            }
#pragma unroll
            for (int mt = 0; mt < 4; mt++)
#pragma unroll
                for (int nt = 0; nt < 2; nt++)
                    mma16816(oc[mt][nt], pa[mt], vb[nt * 2], vb[nt * 2 + 1]);
        }
    }

#pragma unroll
    for (int mt = 0; mt < 4; mt++) {
        int rA = wm * 64 + mt * 16 + qr;
        int rB = rA + 8;
        float iA = 1.f / L[rA], iB = 1.f / L[rB];
#pragma unroll
        for (int nt = 0; nt < 2; nt++) {
            int cn = wn * 16 + nt * 8 + qc;
            long o0 = (long)(b * SEQ + m0 + rA) * D_MODEL + h * HEAD_D + cn;
            long o1 = (long)(b * SEQ + m0 + rB) * D_MODEL + h * HEAD_D + cn;
            *(uint32_t*)(oh + o0) = pack2s(oc[mt][nt][0] * iA, oc[mt][nt][1] * iA);
            *(uint32_t*)(oh + o1) = pack2s(oc[mt][nt][2] * iB, oc[mt][nt][3] * iB);
        }
    }
}

// ================= LayerNorm -> optional fp32 + fp16 =================
__global__ void ln_kernel(const float* __restrict__ x, const float* __restrict__ gam,
                          const float* __restrict__ bet, float* __restrict__ outF,
                          hf* __restrict__ oh) {
    __shared__ float redA[8], redB[8];
    int t = blockIdx.x;
    const float* xr = x + (size_t)t * D_MODEL;
    float v[4]; float s = 0.f;
#pragma unroll
    for (int i = 0; i < 4; i++) { v[i] = xr[threadIdx.x + 256 * i]; s += v[i]; }
#pragma unroll
    for (int o = 16; o; o >>= 1) s += __shfl_xor_sync(~0u, s, o);
    if ((threadIdx.x & 31) == 0) redA[threadIdx.x >> 5] = s;
    __syncthreads();
    if (threadIdx.x == 0) { float r = 0.f; for (int i = 0; i < 8; i++) r += redA[i]; redA[0] = r; }
    __syncthreads();
    float mu = redA[0] * (1.f / D_MODEL);
    float s2 = 0.f;
#pragma unroll
    for (int i = 0; i < 4; i++) { float d = v[i] - mu; s2 += d * d; }
#pragma unroll
    for (int o = 16; o; o >>= 1) s2 += __shfl_xor_sync(~0u, s2, o);
    if ((threadIdx.x & 31) == 0) redB[threadIdx.x >> 5] = s2;
    __syncthreads();
    if (threadIdx.x == 0) { float r = 0.f; for (int i = 0; i < 8; i++) r += redB[i]; redB[0] = r; }
    __syncthreads();
    float rstd = rsqrtf(redB[0] * (1.f / D_MODEL) + 1e-5f);
    size_t base = (size_t)t * D_MODEL;
#pragma unroll
    for (int i = 0; i < 4; i++) {
        int cc = threadIdx.x + 256 * i;
        float r = (v[i] - mu) * rstd * gam[cc] + bet[cc];
        if (outF) outF[base + cc] = r;
        oh[base + cc] = __float2half_rn(r);
    }
}

// ================= router / scan / combine =================
__global__ __launch_bounds__(256)
void router_kernel(const float* __restrict__ h2, const float* __restrict__ wr) {
    int t = blockIdx.x * 8 + (threadIdx.x >> 5);
    int lane = threadIdx.x & 31;
    const float* xr = h2 + (long)t * D_MODEL;
    float acc[8];
#pragma unroll
    for (int e = 0; e < 8; e++) acc[e] = 0.f;
    for (int i = lane; i < D_MODEL; i += 32) {
        float xv = xr[i];
        const float* w = wr + i * 8;
#pragma unroll
        for (int e = 0; e < 8; e++) acc[e] = fmaf(xv, w[e], acc[e]);
    }
#pragma unroll
    for (int o = 16; o; o >>= 1)
#pragma unroll
        for (int e = 0; e < 8; e++) acc[e] += __shfl_xor_sync(~0u, acc[e], o);
    if (lane == 0) {
        float m = acc[0]; int t1 = 0;
#pragma unroll
        for (int e = 1; e < 8; e++) if (acc[e] > m) { m = acc[e]; t1 = e; }
        float s = 0.f, pr[8];
#pragma unroll
        for (int e = 0; e < 8; e++) { pr[e] = expf(acc[e] - m); s += pr[e]; }
        float inv = 1.f / s;
        float m2 = -1e30f; int t2 = 0;
#pragma unroll
        for (int e = 0; e < 8; e++) {
            if (e == t1) continue;
            if (acc[e] > m2) { m2 = acc[e]; t2 = e; }
        }
        g_top1[t] = t1; g_top2[t] = t2;
        g_p1[t] = pr[t1] * inv;
        g_p2[t] = pr[t2] * inv;
    }
}

__global__ __launch_bounds__(256)
void scan_kernel() {
    int tid = threadIdx.x;
    for (int i = tid; i < NEXP * CAPV; i += 256) g_disp[i] = 0;
    __syncthreads();
    int e = tid >> 5;
    int lane = tid & 31;
    unsigned lt = (1u << lane) - 1u;
    int base = 0;
    for (int c0 = 0; c0 < N_TOK; c0 += 32) {
        int t = c0 + lane;
        bool f = (g_top1[t] == e);
        unsigned msk = __ballot_sync(~0u, f);
        if (f) {
            int loc = base + __popc(msk & lt);
            if (loc < CAPV) { g_s1[t] = loc; g_disp[e * CAPV + loc] = t; }
            else g_s1[t] = -1;
        }
        base += __popc(msk);
    }
    for (int c0 = 0; c0 < N_TOK; c0 += 32) {
        int t = c0 + lane;
        bool f = (g_top2[t] == e);
        unsigned msk = __ballot_sync(~0u, f);
        if (f) {
            int loc = base + __popc(msk & lt);
            if (loc < CAPV) { g_s2[t] = loc; g_disp[e * CAPV + loc] = t; }
            else g_s2[t] = -1;
        }
        base += __popc(msk);
    }
    __syncthreads();
    for (int t = tid; t < N_TOK; t += 256) {
        float t1 = (g_s1[t] >= 0) ? g_p1[t] : 0.f;
        float t2 = (g_s2[t] >= 0) ? g_p2[t] : 0.f;
        float den = fmaxf(t1 + t2, 1.1920929e-7f);
        g_g1[t] = t1 / den;
        g_g2[t] = t2 / den;
    }
}

__global__ __launch_bounds__(256)
void combine_kernel(float* __restrict__ out) {
    int t = blockIdx.x;
    int s1 = g_s1[t], s2 = g_s2[t];
    float g1 = g_g1[t], g2 = g_g2[t];
    const float* y1 = (s1 >= 0) ? g_y + ((long)g_top1[t] * CAPV + s1) * D_MODEL : 0;
    const float* y2 = (s2 >= 0) ? g_y + ((long)g_top2[t] * CAPV + s2) * D_MODEL : 0;
    long ro = (long)t * D_MODEL;
#pragma unroll
    for (int i = 0; i < 4; i++) {
        int d = threadIdx.x + 256 * i;
        float a = out[ro + d];
        if (y1) a = fmaf(g1, y1[d], a);
        if (y2) a = fmaf(g2, y2[d], a);
        out[ro + d] = a;
    }
}

// ================= launch =================
extern "C" void kernel_launch(void* const* d_in, const int* in_sizes, int n_in,
                              void* d_out, int out_size) {
    const float* x    = (const float*)d_in[0];
    const float* wq   = (const float*)d_in[1];
    const float* bq   = (const float*)d_in[2];
    const float* wk   = (const float*)d_in[3];
    const float* bk   = (const float*)d_in[4];
    const float* wv   = (const float*)d_in[5];
    const float* bv   = (const float*)d_in[6];
    const float* wo   = (const float*)d_in[7];
    const float* bo   = (const float*)d_in[8];
    const float* ln1g = (const float*)d_in[9];
    const float* ln1b = (const float*)d_in[10];
    const float* ln2g = (const float*)d_in[11];
    const float* ln2b = (const float*)d_in[12];
    const float* wr   = (const float*)d_in[13];
    const float* w1   = (const float*)d_in[14];
    const float* b1   = (const float*)d_in[15];
    const float* w2   = (const float*)d_in[16];
    const float* b2   = (const float*)d_in[17];
    float* out = (float*)d_out;

    hf *wq1, *wk1, *wv1, *wo1, *w11, *w21;
    hf *h1h, *h2h, *qh, *kh, *vh, *ath, *midh;
    float *h2, *y;
    int* disp;
    cudaGetSymbolAddress((void**)&wq1, g_wq1); cudaGetSymbolAddress((void**)&wk1, g_wk1);
    cudaGetSymbolAddress((void**)&wv1, g_wv1); cudaGetSymbolAddress((void**)&wo1, g_wo1);
    cudaGetSymbolAddress((void**)&w11, g_w11); cudaGetSymbolAddress((void**)&w21, g_w21);
    cudaGetSymbolAddress((void**)&h1h, g_h1h); cudaGetSymbolAddress((void**)&h2h, g_h2h);
    cudaGetSymbolAddress((void**)&qh, g_qh);   cudaGetSymbolAddress((void**)&kh, g_kh);
    cudaGetSymbolAddress((void**)&vh, g_vh);   cudaGetSymbolAddress((void**)&ath, g_ath);
    cudaGetSymbolAddress((void**)&midh, g_midh);
    cudaGetSymbolAddress((void**)&h2, g_h2);
    cudaGetSymbolAddress((void**)&y, g_y);
    cudaGetSymbolAddress((void**)&disp, g_disp);

    constexpr int SMEM64  = 3 * (64 * 80 + 8192);
    constexpr int SMEM128 = 3 * (128 * 80 + 8192);
    cudaFuncSetAttribute(gemm_mma<64, false, false, true, true>,
                         cudaFuncAttributeMaxDynamicSharedMemorySize, SMEM64);
    cudaFuncSetAttribute(gemm_mma<64, false, false, false, false>,
                         cudaFuncAttributeMaxDynamicSharedMemorySize, SMEM64);
    cudaFuncSetAttribute(gemm_mma<128, true, true, false, true>,
                         cudaFuncAttributeMaxDynamicSharedMemorySize, SMEM128);
    cudaFuncSetAttribute(gemm_mma<128, false, false, false, false>,
                         cudaFuncAttributeMaxDynamicSharedMemorySize, SMEM128);
    cudaFuncSetAttribute(flash_attn, cudaFuncAttributeMaxDynamicSharedMemorySize, FA_SMEM);

    // 0) weight rounding (16 floats/thread, MLP=4)
    round_attn<<<dim3(64, 1, 4), 256>>>(wq, wk, wv, wo, wq1, wk1, wv1, wo1);
    round_pass<<<2048, 256>>>(w1, w11, 33554432 / 16);
    round_pass<<<2048, 256>>>(w2, w21, 33554432 / 16);

    // 1) LN1 -> fp16
    ln_kernel<<<N_TOK, 256>>>(x, ln1g, ln1b, nullptr, h1h);

    // 2) QKV fused (TM=64)
    gemm_mma<64, false, false, true, true><<<dim3(8, 32, 3), 256, SMEM64>>>(
        h1h, wq1, wk1, wv1, bq, bk, bv,
        nullptr, qh, kh, vh, 0.125f, 1.f, 1.f,
        nullptr, nullptr, 1024, 1024, 0, 0, 0, 0);

    // 3) fused flash attention
    flash_attn<<<dim3(SEQ / 128, NB * N_HEADS), 256, FA_SMEM>>>(qh, kh, vh, ath);

    // 4) O projection + residual (TM=64)
    gemm_mma<64, false, false, false, false><<<dim3(8, 32, 1), 256, SMEM64>>>(
        ath, wo1, nullptr, nullptr, bo, nullptr, nullptr,
        out, nullptr, nullptr, nullptr, 1.f, 0.f, 0.f,
        x, nullptr, 1024, 1024, 0, 0, 0, 0);

    // 5) LN2
    ln_kernel<<<N_TOK, 256>>>(out, ln2g, ln2b, h2, h2h);

    // 6) router + scan
    router_kernel<<<N_TOK / 8, 256>>>(h2, wr);
    scan_kernel<<<1, 256>>>();

    // 7) FFN1 gathered + relu -> fp16 mid (TM=128)
    gemm_mma<128, true, true, false, true><<<dim3(32, 4, 8), 256, SMEM128>>>(
        h2h, w11, nullptr, nullptr, b1, nullptr, nullptr,
        nullptr, midh, nullptr, nullptr, 1.f, 0.f, 0.f,
        nullptr, disp, 1024, 4096, 0, (long)D_MODEL * FFN_D, FFN_D, (long)CAPV * FFN_D);

    // 8) FFN2 -> fp32 y (*0.8) (TM=128)
    gemm_mma<128, false, false, false, false><<<dim3(8, 4, 8), 256, SMEM128>>>(
        midh, w21, nullptr, nullptr, b2, nullptr, nullptr,
        y, nullptr, nullptr, nullptr, 0.8f, 0.f, 0.f,
        nullptr, nullptr, 4096, 1024,
        (long)CAPV * FFN_D, (long)FFN_D * D_MODEL, D_MODEL, (long)CAPV * D_MODEL);

    // 9) combine
    combine_kernel<<<N_TOK, 256>>>(out);
}